// round 1
// baseline (speedup 1.0000x reference)
#include <cuda_runtime.h>
#include <math.h>

#define B_   128
#define TP2  2050
#define T_   2049
#define H_   64
#define G7   448    // 7*H
#define K_   100
#define KE   103    // K+3 rows in in_emb

// Precomputed input projection table: PreTable[e][g] = in_emb[e] @ Wx[:,g] + b[g]
__device__ float g_pretab[KE * G7];

__global__ void build_pretab(const float* __restrict__ in_emb,
                             const float* __restrict__ Wx,
                             const float* __restrict__ bias) {
    int e = blockIdx.x;
    int g = threadIdx.x;
    float s = bias[g];
#pragma unroll
    for (int k = 0; k < H_; ++k)
        s = fmaf(in_emb[e * H_ + k], Wx[k * G7 + g], s);
    g_pretab[e * G7 + g] = s;
}

__device__ __forceinline__ float sigmoidf_(float x) {
    return 1.0f / (1.0f + expf(-x));
}
__device__ __forceinline__ float softplusf_(float x) {
    // numerically stable, matches jax.nn.softplus within fp32 tolerance
    return fmaxf(x, 0.0f) + log1pf(expf(-fabsf(x)));
}

__global__ void __launch_bounds__(G7, 1)
scan_kernel(const int*   __restrict__ event_t,
            const float* __restrict__ dtime_t,
            const float* __restrict__ Wh,
            const float* __restrict__ out_emb,
            float*       __restrict__ out) {
    extern __shared__ float smem[];
    float* pretab_s = smem;                 // KE*G7 floats (184.6 KB)
    float* act      = pretab_s + KE * G7;   // G7 floats
    float* h_s      = act + G7;             // H floats (16B aligned)

    const int tid = threadIdx.x;
    const int bb  = blockIdx.x;

    // --- Register-resident Wh column for this thread's gate output g=tid ---
    float wr[H_];
#pragma unroll
    for (int k = 0; k < H_; ++k) wr[k] = Wh[k * G7 + tid];

    // --- Register-resident out_emb slice: 4 threads per logit output ---
    const int outk = tid >> 2;   // 0..111 (only <100 used)
    const int part = tid & 3;
    float oe[16];
    if (tid < 400) {
#pragma unroll
        for (int i = 0; i < 16; ++i) oe[i] = out_emb[outk * H_ + part * 16 + i];
    } else {
#pragma unroll
        for (int i = 0; i < 16; ++i) oe[i] = 0.f;
    }

    // --- Stage PreTable into shared memory ---
    for (int i = tid; i < KE * G7; i += G7) pretab_s[i] = g_pretab[i];

    if (tid < H_) h_s[tid] = 0.f;
    float c = 0.f, cbv = 0.f;   // cell states live in regs of threads 0..63

    const int*   ev_row = event_t + bb * TP2;
    const float* dt_row = dtime_t + bb * TP2;
    float*       out_row = out + (size_t)bb * T_ * K_;

    __syncthreads();

    int ev = ev_row[0];
    const int blk = tid >> 6;   // gate block id, warp-uniform

    for (int t = 0; t < T_; ++t) {
        // prefetch next event index (broadcast load, hidden under matvec)
        const int ev_next = ev_row[(t + 1 < T_) ? (t + 1) : t];
        const float dtv   = dt_row[t + 1];

        // ---- recurrent matvec: g = pre[ev] + h_{t-1} @ Wh (Wh in regs) ----
        const float4* h4 = (const float4*)h_s;
        float acc0 = pretab_s[ev * G7 + tid];
        float acc1 = 0.f;
#pragma unroll
        for (int k4 = 0; k4 < 16; ++k4) {
            float4 hv = h4[k4];
            acc0 = fmaf(hv.x, wr[4 * k4 + 0], acc0);
            acc1 = fmaf(hv.y, wr[4 * k4 + 1], acc1);
            acc0 = fmaf(hv.z, wr[4 * k4 + 2], acc0);
            acc1 = fmaf(hv.w, wr[4 * k4 + 3], acc1);
        }
        const float g = acc0 + acc1;

        // gate nonlinearity (warp-uniform branch)
        float a;
        if (blk == 2)      a = tanhf(g);        // z
        else if (blk == 6) a = softplusf_(g);   // delta
        else               a = sigmoidf_(g);    // i, f, o, i_bar, f_bar
        act[tid] = a;
        __syncthreads();

        // ---- state update: threads 0..63, one hidden unit each ----
        if (tid < H_) {
            const float iv  = act[tid];
            const float fv  = act[H_ + tid];
            const float zv  = act[2 * H_ + tid];
            const float ov  = act[3 * H_ + tid];
            const float ibv = act[4 * H_ + tid];
            const float fbv = act[5 * H_ + tid];
            const float dv  = act[6 * H_ + tid];
            const float ci  = fmaf(fv, c, iv * zv);
            const float cbi = fmaf(fbv, cbv, ibv * zv);
            const float cn  = fmaf(ci - cbi, expf(-dv * dtv), cbi);
            c   = cn;
            cbv = cbi;
            h_s[tid] = ov * tanhf(cn);
        }
        __syncthreads();

        // ---- fused output projection + softplus for h_t ----
        float s = 0.f;
        if (tid < 400) {
            const float* hp = h_s + part * 16;
#pragma unroll
            for (int i = 0; i < 16; ++i) s = fmaf(hp[i], oe[i], s);
        }
        // reduce 4 partials within aligned 4-lane groups (all lanes converged)
        s += __shfl_down_sync(0xffffffffu, s, 2);
        s += __shfl_down_sync(0xffffffffu, s, 1);
        if (tid < 400 && part == 0)
            out_row[(size_t)t * K_ + outk] = softplusf_(s);

        ev = ev_next;
    }
}

extern "C" void kernel_launch(void* const* d_in, const int* in_sizes, int n_in,
                              void* d_out, int out_size) {
    const int*   ev   = (const int*)  d_in[0];
    const float* dt   = (const float*)d_in[1];
    const float* iemb = (const float*)d_in[2];
    const float* Wx   = (const float*)d_in[3];
    const float* Wh   = (const float*)d_in[4];
    const float* bias = (const float*)d_in[5];
    const float* oemb = (const float*)d_in[6];
    float* out = (float*)d_out;

    const size_t smem_bytes = (size_t)(KE * G7 + G7 + H_ + 16) * sizeof(float);
    cudaFuncSetAttribute(scan_kernel, cudaFuncAttributeMaxDynamicSharedMemorySize,
                         (int)smem_bytes);

    build_pretab<<<KE, G7>>>(iemb, Wx, bias);
    scan_kernel<<<B_, G7, smem_bytes>>>(ev, dt, Wh, oemb, out);
}

// round 2
// speedup vs baseline: 1.1145x; 1.1145x over previous
#include <cuda_runtime.h>
#include <math.h>

#define B_   128
#define TP2  2050
#define T_   2049
#define H_   64
#define G7   448    // 7*H
#define K_   100
#define KE   103    // K+3 rows in in_emb

// Precomputed input projection table: PreTable[e][g] = in_emb[e] @ Wx[:,g] + b[g]
__device__ float g_pretab[KE * G7];

__global__ void build_pretab(const float* __restrict__ in_emb,
                             const float* __restrict__ Wx,
                             const float* __restrict__ bias) {
    int e = blockIdx.x;
    int g = threadIdx.x;
    float s = bias[g];
#pragma unroll
    for (int k = 0; k < H_; ++k)
        s = fmaf(in_emb[e * H_ + k], Wx[k * G7 + g], s);
    g_pretab[e * G7 + g] = s;
}

// ---- packed f32x2 helpers (FFMA2 — ptxas never auto-fuses; PTX-only path) ----
typedef unsigned long long u64;
__device__ __forceinline__ u64 pack2(float x, float y) {
    u64 r; asm("mov.b64 %0, {%1, %2};" : "=l"(r) : "f"(x), "f"(y)); return r;
}
__device__ __forceinline__ float2 unpack2(u64 v) {
    float2 r; asm("mov.b64 {%0, %1}, %2;" : "=f"(r.x), "=f"(r.y) : "l"(v)); return r;
}
__device__ __forceinline__ u64 ffma2_(u64 a, u64 b, u64 c) {
    u64 d; asm("fma.rn.f32x2 %0, %1, %2, %3;" : "=l"(d) : "l"(a), "l"(b), "l"(c));
    return d;
}

// ---- fast activations (tolerance 1e-3; these are ~1e-7 accurate) ----
__device__ __forceinline__ float fast_sigmoid(float x) {
    float e = __expf(-fabsf(x));
    float r = __fdividef(1.0f, 1.0f + e);
    return (x >= 0.f) ? r : 1.0f - r;
}
__device__ __forceinline__ float fast_tanh(float x) {
    float e = __expf(-2.0f * fabsf(x));
    float t = fmaf(-2.0f, __fdividef(e, 1.0f + e), 1.0f);   // (1-e)/(1+e)
    return copysignf(t, x);
}
__device__ __forceinline__ float fast_softplus(float x) {
    float e = __expf(-fabsf(x));
    return fmaxf(x, 0.f) + __logf(1.0f + e);
}

__global__ void __launch_bounds__(G7, 1)
scan_kernel(const int*   __restrict__ event_t,
            const float* __restrict__ dtime_t,
            const float* __restrict__ Wh,
            const float* __restrict__ out_emb,
            float*       __restrict__ out) {
    extern __shared__ float smem[];
    float* pretab_s = smem;                 // KE*G7 floats (184.6 KB)
    float* act      = pretab_s + KE * G7;   // G7 floats
    float* h_s      = act + G7;             // H floats (16B aligned)

    const int tid = threadIdx.x;
    const int bb  = blockIdx.x;

    // --- Register-resident Wh column (packed in k-pairs) for gate g=tid ---
    u64 wr2[H_ / 2];
#pragma unroll
    for (int k2 = 0; k2 < H_ / 2; ++k2)
        wr2[k2] = pack2(Wh[(2 * k2) * G7 + tid], Wh[(2 * k2 + 1) * G7 + tid]);

    // --- Register-resident out_emb slice: 4 threads per logit (packed) ---
    const int outk = tid >> 2;   // 0..111 (only <100 used)
    const int part = tid & 3;
    u64 oe2[8];
    if (tid < 400) {
#pragma unroll
        for (int i = 0; i < 8; ++i)
            oe2[i] = pack2(out_emb[outk * H_ + part * 16 + 2 * i],
                           out_emb[outk * H_ + part * 16 + 2 * i + 1]);
    } else {
#pragma unroll
        for (int i = 0; i < 8; ++i) oe2[i] = 0ull;
    }

    // --- Stage PreTable into shared memory ---
    for (int i = tid; i < KE * G7; i += G7) pretab_s[i] = g_pretab[i];

    if (tid < H_) h_s[tid] = 0.f;
    float c = 0.f, cbv = 0.f;   // cell states live in regs of threads 0..63

    const int*   ev_row  = event_t + bb * TP2;
    const float* dt_row  = dtime_t + bb * TP2;
    float*       out_row = out + (size_t)bb * T_ * K_;

    __syncthreads();

    int ev = ev_row[0];
    const int blk = tid >> 6;   // gate block id, warp-uniform

    for (int t = 0; t < T_; ++t) {
        const int ev_next = ev_row[(t + 1 < T_) ? (t + 1) : t];
        const float dtv   = dt_row[t + 1];

        // ---- recurrent matvec: g = pre[ev] + h_{t-1} @ Wh (packed FFMA2) ----
        const float4* h4 = (const float4*)h_s;
        u64 acc0 = pack2(pretab_s[ev * G7 + tid], 0.f);
        u64 acc1 = 0ull;
#pragma unroll
        for (int k4 = 0; k4 < 16; ++k4) {
            float4 hv = h4[k4];
            acc0 = ffma2_(pack2(hv.x, hv.y), wr2[2 * k4],     acc0);
            acc1 = ffma2_(pack2(hv.z, hv.w), wr2[2 * k4 + 1], acc1);
        }
        float2 a0 = unpack2(acc0), a1 = unpack2(acc1);
        const float g = (a0.x + a1.x) + (a0.y + a1.y);

        // gate nonlinearity (warp-uniform branch)
        float a;
        if (blk == 2)      a = fast_tanh(g);        // z
        else if (blk == 6) a = fast_softplus(g);    // delta
        else               a = fast_sigmoid(g);     // i, f, o, i_bar, f_bar
        act[tid] = a;
        __syncthreads();

        // ---- state update: threads 0..63, one hidden unit each ----
        if (tid < H_) {
            const float iv  = act[tid];
            const float fv  = act[H_ + tid];
            const float zv  = act[2 * H_ + tid];
            const float ov  = act[3 * H_ + tid];
            const float ibv = act[4 * H_ + tid];
            const float fbv = act[5 * H_ + tid];
            const float dv  = act[6 * H_ + tid];
            const float ci  = fmaf(fv, c, iv * zv);
            const float cbi = fmaf(fbv, cbv, ibv * zv);
            const float cn  = fmaf(ci - cbi, __expf(-dv * dtv), cbi);
            c   = cn;
            cbv = cbi;
            h_s[tid] = ov * fast_tanh(cn);
        }
        __syncthreads();

        // ---- fused output projection + softplus for h_t (packed) ----
        float s = 0.f;
        if (tid < 400) {
            const float4* hp = (const float4*)(h_s + part * 16);
            u64 sacc0 = 0ull, sacc1 = 0ull;
#pragma unroll
            for (int i = 0; i < 4; ++i) {
                float4 hv = hp[i];
                sacc0 = ffma2_(pack2(hv.x, hv.y), oe2[2 * i],     sacc0);
                sacc1 = ffma2_(pack2(hv.z, hv.w), oe2[2 * i + 1], sacc1);
            }
            float2 s0 = unpack2(sacc0), s1 = unpack2(sacc1);
            s = (s0.x + s1.x) + (s0.y + s1.y);
        }
        // reduce 4 partials within aligned 4-lane groups (all lanes converged)
        s += __shfl_down_sync(0xffffffffu, s, 2);
        s += __shfl_down_sync(0xffffffffu, s, 1);
        if (tid < 400 && part == 0)
            out_row[(size_t)t * K_ + outk] = fast_softplus(s);

        ev = ev_next;
    }
}

extern "C" void kernel_launch(void* const* d_in, const int* in_sizes, int n_in,
                              void* d_out, int out_size) {
    const int*   ev   = (const int*)  d_in[0];
    const float* dt   = (const float*)d_in[1];
    const float* iemb = (const float*)d_in[2];
    const float* Wx   = (const float*)d_in[3];
    const float* Wh   = (const float*)d_in[4];
    const float* bias = (const float*)d_in[5];
    const float* oemb = (const float*)d_in[6];
    float* out = (float*)d_out;

    const size_t smem_bytes = (size_t)(KE * G7 + G7 + H_ + 16) * sizeof(float);
    cudaFuncSetAttribute(scan_kernel, cudaFuncAttributeMaxDynamicSharedMemorySize,
                         (int)smem_bytes);

    build_pretab<<<KE, G7>>>(iemb, Wx, bias);
    scan_kernel<<<B_, G7, smem_bytes>>>(ev, dt, Wh, oemb, out);
}

// round 3
// speedup vs baseline: 1.1678x; 1.0478x over previous
#include <cuda_runtime.h>
#include <math.h>

#define B_   128
#define TP2  2050
#define T_   2049
#define H_   64
#define G7   448    // 7*H
#define K_   100
#define KE   103    // K+3 rows in in_emb
#define HPAD 64

// Precomputed input projection table: PreTable[e][g] = in_emb[e] @ Wx[:,g] + b[g]
__device__ float g_pretab[KE * G7];

__global__ void build_pretab(const float* __restrict__ in_emb,
                             const float* __restrict__ Wx,
                             const float* __restrict__ bias) {
    int e = blockIdx.x;
    int g = threadIdx.x;
    float s = bias[g];
#pragma unroll
    for (int k = 0; k < H_; ++k)
        s = fmaf(in_emb[e * H_ + k], Wx[k * G7 + g], s);
    g_pretab[e * G7 + g] = s;
}

// ---- packed f32x2 helpers ----
typedef unsigned long long u64;
__device__ __forceinline__ u64 pack2(float x, float y) {
    u64 r; asm("mov.b64 %0, {%1, %2};" : "=l"(r) : "f"(x), "f"(y)); return r;
}
__device__ __forceinline__ float2 unpack2(u64 v) {
    float2 r; asm("mov.b64 {%0, %1}, %2;" : "=f"(r.x), "=f"(r.y) : "l"(v)); return r;
}
__device__ __forceinline__ u64 ffma2_(u64 a, u64 b, u64 c) {
    u64 d; asm("fma.rn.f32x2 %0, %1, %2, %3;" : "=l"(d) : "l"(a), "l"(b), "l"(c));
    return d;
}
__device__ __forceinline__ u64 fadd2_(u64 a, u64 b) {
    u64 d; asm("add.rn.f32x2 %0, %1, %2;" : "=l"(d) : "l"(a), "l"(b));
    return d;
}

// ---- fast activations (inf-safe without branches) ----
__device__ __forceinline__ float fast_sigmoid(float x) {
    // x<<0: expf->inf, fdividef(1,inf)=0 ; x>>0: expf->0, ->1
    return __fdividef(1.0f, 1.0f + __expf(-x));
}
__device__ __forceinline__ float fast_tanh(float x) {
    // 2/(1+e^{-2x}) - 1 ; e->inf gives -1, e->0 gives +1
    float e = __expf(-2.0f * x);
    return __fdividef(2.0f, 1.0f + e) - 1.0f;
}
__device__ __forceinline__ float fast_softplus(float x) {
    float e = __expf(-fabsf(x));
    return fmaxf(x, 0.f) + __logf(1.0f + e);
}

__device__ __forceinline__ void bar_sync(int id, int cnt) {
    asm volatile("bar.sync %0, %1;" :: "r"(id), "r"(cnt) : "memory");
}
__device__ __forceinline__ void bar_arrive(int id, int cnt) {
    asm volatile("bar.arrive %0, %1;" :: "r"(id), "r"(cnt) : "memory");
}

__global__ void __launch_bounds__(G7, 1)
scan_kernel(const int*   __restrict__ event_t,
            const float* __restrict__ dtime_t,
            const float* __restrict__ Wh,
            const float* __restrict__ out_emb,
            float*       __restrict__ out) {
    extern __shared__ float smem[];
    float* pretab_s = smem;                 // KE*G7 floats
    float* act      = pretab_s + KE * G7;   // G7 floats
    float* h_s      = act + G7;             // 2*HPAD floats (double buffered)

    const int tid = threadIdx.x;
    const int bb  = blockIdx.x;

    // --- Register-resident Wh column (k-pairs packed) for gate g=tid ---
    u64 wr2[H_ / 2];
#pragma unroll
    for (int k2 = 0; k2 < H_ / 2; ++k2)
        wr2[k2] = pack2(Wh[(2 * k2) * G7 + tid], Wh[(2 * k2 + 1) * G7 + tid]);

    // --- out_emb slices: 2 threads per logit, tid 64..263 ---
    const int ot   = tid - 64;
    const int outk = ot >> 1;     // 0..191 (only <100 used)
    const int part = ot & 1;
    u64 oe2[16];
    if (ot >= 0 && outk < K_) {
#pragma unroll
        for (int i = 0; i < 16; ++i)
            oe2[i] = pack2(out_emb[outk * H_ + part * 32 + 2 * i],
                           out_emb[outk * H_ + part * 32 + 2 * i + 1]);
    } else {
#pragma unroll
        for (int i = 0; i < 16; ++i) oe2[i] = 0ull;
    }

    // --- Stage PreTable into shared memory ---
    for (int i = tid; i < KE * G7; i += G7) pretab_s[i] = g_pretab[i];

    if (tid < H_) { h_s[HPAD + tid] = 0.f; }   // initial h lives in buf1
    float c = 0.f, cbv = 0.f;                  // cell states in regs of tid<64

    const int*   ev_row  = event_t + bb * TP2;
    const float* dt_row  = dtime_t + bb * TP2;
    float*       out_row = out + (size_t)bb * T_ * K_;

    __syncthreads();

    int   ev  = ev_row[0];
    float dtv = dt_row[1];
    const int blk = tid >> 6;   // gate block id, warp-uniform

    for (int t = 0; t < T_; ++t) {
        // prefetch next step's event/dt (broadcast global loads, long latency ok)
        const int   ev_next = ev_row[(t + 1 < T_) ? (t + 1) : (T_ - 1)];
        const float dt_next = dt_row[(t + 2 < TP2) ? (t + 2) : (TP2 - 1)];

        const float* hr = (t & 1) ? h_s : (h_s + HPAD);   // h_{t-1}
        float*       hw = (t & 1) ? (h_s + HPAD) : h_s;   // h_t

        // ---- recurrent matvec: g = pre[ev] + h_{t-1} @ Wh (f32x2, 4 chains) ----
        const ulonglong2* h2 = (const ulonglong2*)hr;
        u64 a0 = pack2(pretab_s[ev * G7 + tid], 0.f);
        u64 a1 = 0ull, a2 = 0ull, a3 = 0ull;
#pragma unroll
        for (int k4 = 0; k4 < 16; k4 += 2) {
            ulonglong2 hp = h2[k4];
            a0 = ffma2_(hp.x, wr2[2 * k4],     a0);
            a1 = ffma2_(hp.y, wr2[2 * k4 + 1], a1);
            ulonglong2 hq = h2[k4 + 1];
            a2 = ffma2_(hq.x, wr2[2 * k4 + 2], a2);
            a3 = ffma2_(hq.y, wr2[2 * k4 + 3], a3);
        }
        float2 r = unpack2(fadd2_(fadd2_(a0, a1), fadd2_(a2, a3)));
        const float g = r.x + r.y;

        // ---- gate nonlinearity (warp-uniform branch) ----
        float a;
        if (blk == 2)      a = fast_tanh(g);                        // z
        else if (blk == 6) a = __expf(-dtv * fast_softplus(g));     // e = exp(-delta*dt)
        else               a = fast_sigmoid(g);                     // i,f,o,ib,fb
        act[tid] = a;

        if (tid < H_) {
            // ======== update warps (0-1) ========
            bar_sync(1, G7);                      // wait for all 448 gate values
            const float iv  = act[tid];
            const float fv  = act[H_ + tid];
            const float zv  = act[2 * H_ + tid];
            const float ov  = act[3 * H_ + tid];
            const float ibv = act[4 * H_ + tid];
            const float fbv = act[5 * H_ + tid];
            const float ev_ = act[6 * H_ + tid];  // exp(-delta*dt), precomputed
            const float ci  = fmaf(fv, c, iv * zv);
            const float cbi = fmaf(fbv, cbv, ibv * zv);
            const float cn  = fmaf(ci - cbi, ev_, cbi);
            c   = cn;
            cbv = cbi;
            hw[tid] = ov * fast_tanh(cn);
            bar_sync(2, G7);                      // publish h_t
        } else {
            // ======== out-proj warps (2-13): overlap with update ========
            bar_arrive(1, G7);                    // signal gates ready, don't wait
            // output projection for step t-1 (reads hr == h_{t-1})
            const ulonglong2* hp2 = (const ulonglong2*)(hr + part * 32);
            u64 s0 = 0ull, s1 = 0ull;
#pragma unroll
            for (int i = 0; i < 8; i += 2) {
                ulonglong2 hv = hp2[i];
                s0 = ffma2_(hv.x, oe2[2 * i],     s0);
                s1 = ffma2_(hv.y, oe2[2 * i + 1], s1);
                ulonglong2 hu = hp2[i + 1];
                s0 = ffma2_(hu.x, oe2[2 * i + 2], s0);
                s1 = ffma2_(hu.y, oe2[2 * i + 3], s1);
            }
            float2 sr = unpack2(fadd2_(s0, s1));
            float s = sr.x + sr.y;
            s += __shfl_down_sync(0xffffffffu, s, 1);   // all 32 lanes converged
            if (t > 0 && outk < K_ && part == 0)
                out_row[(size_t)(t - 1) * K_ + outk] = fast_softplus(s);
            bar_sync(2, G7);                      // wait for h_t
        }

        ev  = ev_next;
        dtv = dt_next;
    }

    // ---- drain: out-proj for final step t = T_-1 (h in buf (T_-1)&1 = buf0) ----
    if (tid >= H_) {
        const float* hl = h_s;   // (T_-1)&1 == 0
        const ulonglong2* hp2 = (const ulonglong2*)(hl + part * 32);
        u64 s0 = 0ull, s1 = 0ull;
#pragma unroll
        for (int i = 0; i < 8; ++i) {
            ulonglong2 hv = hp2[i];
            s0 = ffma2_(hv.x, oe2[2 * i],     s0);
            s1 = ffma2_(hv.y, oe2[2 * i + 1], s1);
        }
        float2 sr = unpack2(fadd2_(s0, s1));
        float s = sr.x + sr.y;
        s += __shfl_down_sync(0xffffffffu, s, 1);
        if (outk < K_ && part == 0)
            out_row[(size_t)(T_ - 1) * K_ + outk] = fast_softplus(s);
    }
}

extern "C" void kernel_launch(void* const* d_in, const int* in_sizes, int n_in,
                              void* d_out, int out_size) {
    const int*   ev   = (const int*)  d_in[0];
    const float* dt   = (const float*)d_in[1];
    const float* iemb = (const float*)d_in[2];
    const float* Wx   = (const float*)d_in[3];
    const float* Wh   = (const float*)d_in[4];
    const float* bias = (const float*)d_in[5];
    const float* oemb = (const float*)d_in[6];
    float* out = (float*)d_out;

    const size_t smem_bytes = (size_t)(KE * G7 + G7 + 2 * HPAD + 16) * sizeof(float);
    cudaFuncSetAttribute(scan_kernel, cudaFuncAttributeMaxDynamicSharedMemorySize,
                         (int)smem_bytes);

    build_pretab<<<KE, G7>>>(iemb, Wx, bias);
    scan_kernel<<<B_, G7, smem_bytes>>>(ev, dt, Wh, oemb, out);
}